// round 4
// baseline (speedup 1.0000x reference)
#include <cuda_runtime.h>
#include <math.h>

#define BB 64
#define TT 512
#define II 256
#define HH 512
#define CC 128

// Scratch (static device allocations are allowed; cudaMalloc is not)
__device__ float g_gates[(size_t)TT * BB * 4 * HH];   // [t][b][4H]  256 MB
__device__ float g_hs[(size_t)TT * BB * HH];          // [t][b][H]    64 MB
__device__ float g_h[2][BB * HH];                     // ping-pong h state
__device__ unsigned int g_bar_count;
__device__ unsigned int g_bar_gen;

// ---------------------------------------------------------------------------
// Grid-wide barrier (all CTAs co-resident: grid=128 < 148 SMs). Generation-
// counting, monotonic across graph replays (count returns to 0 each launch).
// ---------------------------------------------------------------------------
__device__ __forceinline__ void grid_barrier() {
    __syncthreads();
    if (threadIdx.x == 0) {
        unsigned int my = *((volatile unsigned int*)&g_bar_gen);
        __threadfence();
        unsigned int arrived = atomicAdd(&g_bar_count, 1u);
        if (arrived == gridDim.x - 1) {
            atomicExch(&g_bar_count, 0u);
            __threadfence();
            atomicAdd(&g_bar_gen, 1u);
        } else {
            while (*((volatile unsigned int*)&g_bar_gen) == my) { __nanosleep(64); }
        }
        __threadfence();
    }
    __syncthreads();
}

__device__ __forceinline__ float sigmoidf_(float x) {
    return 1.0f / (1.0f + expf(-x));
}

// ---------------------------------------------------------------------------
// Phase 1: G[t][b][n] = x[b][t][:] . W_ih[n][:] + b_ih[n] + b_hh[n]
// M = B*T = 32768 (row m = b*T + t), N = 2048, K = 256.
// 128x128 tile, BK=8, 256 threads, 8x8 per thread (split 4+4 for conflict-free LDS).
// ---------------------------------------------------------------------------
__global__ void __launch_bounds__(256) gates_gemm(
    const float* __restrict__ x,
    const float* __restrict__ W_ih,
    const float* __restrict__ b_ih,
    const float* __restrict__ b_hh)
{
    __shared__ float As[8][128];
    __shared__ float Bs[8][128];

    const int n0 = blockIdx.x * 128;
    const int m0 = blockIdx.y * 128;
    const int tid = threadIdx.x;
    const int tx = tid & 15;       // 0..15
    const int ty = tid >> 4;       // 0..15

    float acc[8][8];
#pragma unroll
    for (int i = 0; i < 8; i++)
#pragma unroll
        for (int j = 0; j < 8; j++) acc[i][j] = 0.0f;

    const int lr = tid >> 1;            // 0..127
    const int lk = (tid & 1) * 4;       // 0 or 4

    for (int k0 = 0; k0 < II; k0 += 8) {
        // A tile: x rows m0..m0+127, cols k0..k0+7
        {
            float4 v = *(const float4*)(x + (size_t)(m0 + lr) * II + k0 + lk);
            As[lk + 0][lr] = v.x; As[lk + 1][lr] = v.y;
            As[lk + 2][lr] = v.z; As[lk + 3][lr] = v.w;
        }
        // B tile: W_ih rows n0..n0+127, cols k0..k0+7  (Bs[k][n])
        {
            float4 v = *(const float4*)(W_ih + (size_t)(n0 + lr) * II + k0 + lk);
            Bs[lk + 0][lr] = v.x; Bs[lk + 1][lr] = v.y;
            Bs[lk + 2][lr] = v.z; Bs[lk + 3][lr] = v.w;
        }
        __syncthreads();
#pragma unroll
        for (int k = 0; k < 8; k++) {
            float a[8], b[8];
            float4 a0 = *(const float4*)&As[k][ty * 4];
            float4 a1 = *(const float4*)&As[k][64 + ty * 4];
            float4 b0 = *(const float4*)&Bs[k][tx * 4];
            float4 b1 = *(const float4*)&Bs[k][64 + tx * 4];
            a[0]=a0.x; a[1]=a0.y; a[2]=a0.z; a[3]=a0.w;
            a[4]=a1.x; a[5]=a1.y; a[6]=a1.z; a[7]=a1.w;
            b[0]=b0.x; b[1]=b0.y; b[2]=b0.z; b[3]=b0.w;
            b[4]=b1.x; b[5]=b1.y; b[6]=b1.z; b[7]=b1.w;
#pragma unroll
            for (int i = 0; i < 8; i++)
#pragma unroll
                for (int j = 0; j < 8; j++)
                    acc[i][j] = fmaf(a[i], b[j], acc[i][j]);
        }
        __syncthreads();
    }

    // Write: row m = b*T + t  ->  G row index (t*B + b)
#pragma unroll
    for (int i = 0; i < 8; i++) {
        int m = m0 + (i >> 2) * 64 + ty * 4 + (i & 3);
        int bb = m >> 9;          // / T
        int tt = m & 511;         // % T
        size_t row = ((size_t)tt * BB + bb) * (4 * HH);
#pragma unroll
        for (int j = 0; j < 8; j++) {
            int n = n0 + (j >> 2) * 64 + tx * 4 + (j & 3);
            g_gates[row + n] = acc[i][j] + b_ih[n] + b_hh[n];
        }
    }
}

// ---------------------------------------------------------------------------
// Phase 2: persistent recurrence. 128 CTAs x 256 threads.
// CTA owns hidden units j0..j0+3 for all 64 batches; thread = (b, jl).
// W_hh slice (16 rows x 512) lives in padded shared memory for all 512 steps.
// h state ping-pongs in L2 (ldcg/stcg).
// ---------------------------------------------------------------------------
__global__ void __launch_bounds__(256) lstm_recur(const float* __restrict__ W_hh)
{
    const int tid = threadIdx.x;
    const int b  = tid >> 2;            // 0..63
    const int jl = tid & 3;             // 0..3
    const int j0 = blockIdx.x * 4;
    const int j  = j0 + jl;

    // Padded float4 layout: idx(jl, gate, k4) = jl*517 + gate*129 + k4
    // -> per-warp LDS addresses for the 4 jl land in disjoint bank groups.
    __shared__ float4 Ws4[4 * 517];

    for (int idx = tid; idx < 16 * 128; idx += 256) {
        int row = idx >> 7;             // 0..15 = gate*4 + jj
        int k4  = idx & 127;
        int g   = row >> 2;
        int jj  = row & 3;
        float4 v = *(const float4*)(W_hh + ((size_t)(g * HH + j0 + jj)) * HH + k4 * 4);
        Ws4[jj * 517 + g * 129 + k4] = v;
    }

    // init read-buffer h to 0 (fresh every launch / graph replay)
    __stcg(&g_h[0][b * HH + j], 0.0f);
    float c = 0.0f;
    __syncthreads();
    grid_barrier();

    const float4* Wi = &Ws4[jl * 517 + 0 * 129];
    const float4* Wf = &Ws4[jl * 517 + 1 * 129];
    const float4* Wg = &Ws4[jl * 517 + 2 * 129];
    const float4* Wo = &Ws4[jl * 517 + 3 * 129];

    for (int t = 0; t < TT; t++) {
        const float4* h4 = (const float4*)(&g_h[t & 1][b * HH]);
        float a0 = 0.f, a1 = 0.f, a2 = 0.f, a3 = 0.f;
#pragma unroll 4
        for (int k4 = 0; k4 < 128; k4++) {
            float4 hv = __ldcg(h4 + k4);
            float4 wi = Wi[k4], wf = Wf[k4], wg = Wg[k4], wo = Wo[k4];
            a0 = fmaf(hv.x, wi.x, a0); a0 = fmaf(hv.y, wi.y, a0);
            a0 = fmaf(hv.z, wi.z, a0); a0 = fmaf(hv.w, wi.w, a0);
            a1 = fmaf(hv.x, wf.x, a1); a1 = fmaf(hv.y, wf.y, a1);
            a1 = fmaf(hv.z, wf.z, a1); a1 = fmaf(hv.w, wf.w, a1);
            a2 = fmaf(hv.x, wg.x, a2); a2 = fmaf(hv.y, wg.y, a2);
            a2 = fmaf(hv.z, wg.z, a2); a2 = fmaf(hv.w, wg.w, a2);
            a3 = fmaf(hv.x, wo.x, a3); a3 = fmaf(hv.y, wo.y, a3);
            a3 = fmaf(hv.z, wo.z, a3); a3 = fmaf(hv.w, wo.w, a3);
        }
        const float* xg = &g_gates[((size_t)t * BB + b) * (4 * HH)];
        float gi = sigmoidf_(xg[j]            + a0);
        float gf = sigmoidf_(xg[HH + j]       + a1);
        float gg = tanhf    (xg[2 * HH + j]   + a2);
        float go = sigmoidf_(xg[3 * HH + j]   + a3);
        c = gf * c + gi * gg;
        float h = go * tanhf(c);
        __stcg(&g_h[(t + 1) & 1][b * HH + j], h);
        g_hs[((size_t)t * BB + b) * HH + j] = h;
        grid_barrier();
    }
}

// ---------------------------------------------------------------------------
// Phase 3: out[b][t][c] = hs[t][b][:] . W_fc[c][:] + b_fc[c]
// M = 32768 (row m = t*B + b), N = 128, K = 512. Same tiling.
// ---------------------------------------------------------------------------
__global__ void __launch_bounds__(256) fc_gemm(
    const float* __restrict__ W_fc,
    const float* __restrict__ b_fc,
    float* __restrict__ out)
{
    __shared__ float As[8][128];
    __shared__ float Bs[8][128];

    const int m0 = blockIdx.x * 128;
    const int tid = threadIdx.x;
    const int tx = tid & 15;
    const int ty = tid >> 4;

    float acc[8][8];
#pragma unroll
    for (int i = 0; i < 8; i++)
#pragma unroll
        for (int j = 0; j < 8; j++) acc[i][j] = 0.0f;

    const int lr = tid >> 1;
    const int lk = (tid & 1) * 4;

    for (int k0 = 0; k0 < HH; k0 += 8) {
        {
            float4 v = *(const float4*)(g_hs + (size_t)(m0 + lr) * HH + k0 + lk);
            As[lk + 0][lr] = v.x; As[lk + 1][lr] = v.y;
            As[lk + 2][lr] = v.z; As[lk + 3][lr] = v.w;
        }
        {
            float4 v = *(const float4*)(W_fc + (size_t)lr * HH + k0 + lk);
            Bs[lk + 0][lr] = v.x; Bs[lk + 1][lr] = v.y;
            Bs[lk + 2][lr] = v.z; Bs[lk + 3][lr] = v.w;
        }
        __syncthreads();
#pragma unroll
        for (int k = 0; k < 8; k++) {
            float a[8], b[8];
            float4 a0 = *(const float4*)&As[k][ty * 4];
            float4 a1 = *(const float4*)&As[k][64 + ty * 4];
            float4 b0 = *(const float4*)&Bs[k][tx * 4];
            float4 b1 = *(const float4*)&Bs[k][64 + tx * 4];
            a[0]=a0.x; a[1]=a0.y; a[2]=a0.z; a[3]=a0.w;
            a[4]=a1.x; a[5]=a1.y; a[6]=a1.z; a[7]=a1.w;
            b[0]=b0.x; b[1]=b0.y; b[2]=b0.z; b[3]=b0.w;
            b[4]=b1.x; b[5]=b1.y; b[6]=b1.z; b[7]=b1.w;
#pragma unroll
            for (int i = 0; i < 8; i++)
#pragma unroll
                for (int j = 0; j < 8; j++)
                    acc[i][j] = fmaf(a[i], b[j], acc[i][j]);
        }
        __syncthreads();
    }

    // row m = t*B + b  ->  out[(b*T + t)*C + c]
#pragma unroll
    for (int i = 0; i < 8; i++) {
        int m = m0 + (i >> 2) * 64 + ty * 4 + (i & 3);
        int bb = m & 63;
        int tt = m >> 6;
        size_t orow = ((size_t)bb * TT + tt) * CC;
#pragma unroll
        for (int j = 0; j < 8; j++) {
            int cc = (j >> 2) * 64 + tx * 4 + (j & 3);
            out[orow + cc] = acc[i][j] + b_fc[cc];
        }
    }
}

// ---------------------------------------------------------------------------
extern "C" void kernel_launch(void* const* d_in, const int* in_sizes, int n_in,
                              void* d_out, int out_size)
{
    const float* x    = (const float*)d_in[0];
    const float* W_ih = (const float*)d_in[1];
    const float* W_hh = (const float*)d_in[2];
    const float* b_ih = (const float*)d_in[3];
    const float* b_hh = (const float*)d_in[4];
    const float* W_fc = (const float*)d_in[5];
    const float* b_fc = (const float*)d_in[6];
    float* out = (float*)d_out;

    dim3 g1(4 * HH / 128, (BB * TT) / 128);   // (16, 256)
    gates_gemm<<<g1, 256>>>(x, W_ih, b_ih, b_hh);

    lstm_recur<<<HH / 4, 256>>>(W_hh);        // 128 CTAs, co-resident

    fc_gemm<<<(BB * TT) / 128, 256>>>(W_fc, b_fc, out);
}

// round 5
// speedup vs baseline: 1.7793x; 1.7793x over previous
#include <cuda_runtime.h>
#include <math.h>

#define BB 64
#define TT 512
#define II 256
#define HH 512
#define CC 128

// Scratch (static device allocations are allowed; cudaMalloc is not)
__device__ float g_gates[(size_t)TT * BB * 4 * HH];   // [t][b][4H]  256 MB
__device__ float g_hs[(size_t)TT * BB * HH];          // [t][b][H]    64 MB
__device__ float g_h[2][BB * HH];                     // ping-pong h state
__device__ unsigned int g_bar_count;
__device__ unsigned int g_bar_gen;

// ---------------------------------------------------------------------------
// Grid-wide barrier (all CTAs co-resident: grid=128 < 148 SMs). Generation-
// counting, monotonic across graph replays. All threads fence (release) so
// every thread's stcg h-writes are L2-visible before any CTA proceeds.
// ---------------------------------------------------------------------------
__device__ __forceinline__ void grid_barrier() {
    __threadfence();
    __syncthreads();
    if (threadIdx.x == 0) {
        unsigned int my = *((volatile unsigned int*)&g_bar_gen);
        unsigned int arrived = atomicAdd(&g_bar_count, 1u);
        if (arrived == gridDim.x - 1) {
            atomicExch(&g_bar_count, 0u);
            __threadfence();
            atomicAdd(&g_bar_gen, 1u);
        } else {
            while (*((volatile unsigned int*)&g_bar_gen) == my) { __nanosleep(32); }
        }
        __threadfence();
    }
    __syncthreads();
}

__device__ __forceinline__ float sigmoidf_(float x) {
    return 1.0f / (1.0f + expf(-x));
}

// Packed dual-FMA: acc(lo,hi) += a(lo,hi) * b(lo,hi)   (ptxas never auto-fuses)
__device__ __forceinline__ void ffma2(unsigned long long& acc,
                                      unsigned long long a,
                                      unsigned long long b) {
    asm("fma.rn.f32x2 %0, %1, %2, %0;" : "+l"(acc) : "l"(a), "l"(b));
}

__device__ __forceinline__ float pairsum(unsigned long long v) {
    float2 f = *(float2*)&v;
    return f.x + f.y;
}

// ---------------------------------------------------------------------------
// Phase 1: G[t][b][n] = x[b][t][:] . W_ih[n][:] + b_ih[n] + b_hh[n]
// (unchanged this round)
// ---------------------------------------------------------------------------
__global__ void __launch_bounds__(256) gates_gemm(
    const float* __restrict__ x,
    const float* __restrict__ W_ih,
    const float* __restrict__ b_ih,
    const float* __restrict__ b_hh)
{
    __shared__ float As[8][128];
    __shared__ float Bs[8][128];

    const int n0 = blockIdx.x * 128;
    const int m0 = blockIdx.y * 128;
    const int tid = threadIdx.x;
    const int tx = tid & 15;
    const int ty = tid >> 4;

    float acc[8][8];
#pragma unroll
    for (int i = 0; i < 8; i++)
#pragma unroll
        for (int j = 0; j < 8; j++) acc[i][j] = 0.0f;

    const int lr = tid >> 1;
    const int lk = (tid & 1) * 4;

    for (int k0 = 0; k0 < II; k0 += 8) {
        {
            float4 v = *(const float4*)(x + (size_t)(m0 + lr) * II + k0 + lk);
            As[lk + 0][lr] = v.x; As[lk + 1][lr] = v.y;
            As[lk + 2][lr] = v.z; As[lk + 3][lr] = v.w;
        }
        {
            float4 v = *(const float4*)(W_ih + (size_t)(n0 + lr) * II + k0 + lk);
            Bs[lk + 0][lr] = v.x; Bs[lk + 1][lr] = v.y;
            Bs[lk + 2][lr] = v.z; Bs[lk + 3][lr] = v.w;
        }
        __syncthreads();
#pragma unroll
        for (int k = 0; k < 8; k++) {
            float a[8], b[8];
            float4 a0 = *(const float4*)&As[k][ty * 4];
            float4 a1 = *(const float4*)&As[k][64 + ty * 4];
            float4 b0 = *(const float4*)&Bs[k][tx * 4];
            float4 b1 = *(const float4*)&Bs[k][64 + tx * 4];
            a[0]=a0.x; a[1]=a0.y; a[2]=a0.z; a[3]=a0.w;
            a[4]=a1.x; a[5]=a1.y; a[6]=a1.z; a[7]=a1.w;
            b[0]=b0.x; b[1]=b0.y; b[2]=b0.z; b[3]=b0.w;
            b[4]=b1.x; b[5]=b1.y; b[6]=b1.z; b[7]=b1.w;
#pragma unroll
            for (int i = 0; i < 8; i++)
#pragma unroll
                for (int j = 0; j < 8; j++)
                    acc[i][j] = fmaf(a[i], b[j], acc[i][j]);
        }
        __syncthreads();
    }

#pragma unroll
    for (int i = 0; i < 8; i++) {
        int m = m0 + (i >> 2) * 64 + ty * 4 + (i & 3);
        int bb = m >> 9;
        int tt = m & 511;
        size_t row = ((size_t)tt * BB + bb) * (4 * HH);
#pragma unroll
        for (int j = 0; j < 8; j++) {
            int n = n0 + (j >> 2) * 64 + tx * 4 + (j & 3);
            g_gates[row + n] = acc[i][j] + b_ih[n] + b_hh[n];
        }
    }
}

// ---------------------------------------------------------------------------
// Phase 2: persistent recurrence, 2-D sharded.
// Grid = 128 CTAs: blockIdx -> (bg in 0..3, jg in 0..31).
// CTA owns batches b0..b0+15 and hidden units j0..j0+15 (256 threads, one
// (b, j) cell each). Weights (16 units x 4 gates x 512) live in padded smem
// for the whole kernel; h for the CTA's 16 batches is staged into padded smem
// each step (kills the 4x redundant L2 broadcast reads of the old layout).
// Dot products run as packed fma.rn.f32x2 over (k, k+1) pairs taken straight
// from the b64 halves of the float4 smem loads (no repacking MOVs).
// ---------------------------------------------------------------------------
#define W_PITCH 129                 // float4 units per (jl,gate) row (pad vs 128)
#define H_PITCH 516                 // floats per staged h row (pad vs 512)
#define WSM_F4  (16 * 4 * W_PITCH)              // float4 count for weights
#define SMEM_RECUR ((WSM_F4 * 16) + (16 * H_PITCH * 4))   // bytes

__global__ void __launch_bounds__(256) lstm_recur(const float* __restrict__ W_hh)
{
    extern __shared__ float smem[];
    float4* Ws4 = (float4*)smem;                      // [ (jl*4+gate)*W_PITCH + k4 ]
    float*  hsm = smem + WSM_F4 * 4;                  // [ bl*H_PITCH + k ]

    const int tid = threadIdx.x;
    const int bl  = tid & 15;          // batch-lane 0..15
    const int jl  = tid >> 4;          // unit-lane  0..15  (warp: 2 jl x 16 bl)
    const int bg  = blockIdx.x & 3;
    const int jg  = blockIdx.x >> 2;
    const int b   = bg * 16 + bl;
    const int j   = jg * 16 + jl;
    const int j0  = jg * 16;

    // Load this CTA's W_hh slice: rows (gate*H + j0+u), u=0..15. 8192 float4s.
    for (int idx = tid; idx < 16 * 4 * 128; idx += 256) {
        int u   = idx >> 9;            // 0..15
        int rem = idx & 511;
        int g   = rem >> 7;            // 0..3
        int k4  = rem & 127;
        Ws4[(u * 4 + g) * W_PITCH + k4] =
            *(const float4*)(W_hh + ((size_t)(g * HH + j0 + u)) * HH + k4 * 4);
    }

    // init read-buffer h to 0 (fresh every launch / graph replay)
    __stcg(&g_h[0][b * HH + j], 0.0f);
    float c = 0.0f;
    grid_barrier();

    const ulonglong2* Wi = (const ulonglong2*)(Ws4 + (jl * 4 + 0) * W_PITCH);
    const ulonglong2* Wf = (const ulonglong2*)(Ws4 + (jl * 4 + 1) * W_PITCH);
    const ulonglong2* Wg = (const ulonglong2*)(Ws4 + (jl * 4 + 2) * W_PITCH);
    const ulonglong2* Wo = (const ulonglong2*)(Ws4 + (jl * 4 + 3) * W_PITCH);
    const ulonglong2* Hr = (const ulonglong2*)(hsm + bl * H_PITCH);

    for (int t = 0; t < TT; t++) {
        // Stage h[t] for this CTA's 16 batches into smem (L2-coherent reads).
        const float* hsrc = &g_h[t & 1][(bg * 16) * HH];
#pragma unroll
        for (int i = 0; i < 8; i++) {
            int idx  = i * 256 + tid;          // 0..2047 float4s
            int brow = idx >> 7;               // 0..15
            int k4   = idx & 127;
            float4 v = __ldcg((const float4*)(hsrc + (size_t)brow * HH) + k4);
            *(float4*)(hsm + brow * H_PITCH + k4 * 4) = v;
        }

        // Prefetch the 4 precomputed gate inputs (DRAM) — latency hidden by
        // the dot-product loop below.
        const float* xg = &g_gates[((size_t)t * BB + b) * (4 * HH) + j];
        float xi = __ldcg(xg);
        float xf = __ldcg(xg + HH);
        float xgg = __ldcg(xg + 2 * HH);
        float xo = __ldcg(xg + 3 * HH);

        __syncthreads();   // staged h visible

        unsigned long long ai = 0ull, af = 0ull, ag = 0ull, ao = 0ull;
#pragma unroll 8
        for (int k4 = 0; k4 < 128; k4++) {
            ulonglong2 h2 = Hr[k4];
            ulonglong2 wi = Wi[k4];
            ulonglong2 wf = Wf[k4];
            ulonglong2 wg = Wg[k4];
            ulonglong2 wo = Wo[k4];
            ffma2(ai, h2.x, wi.x); ffma2(ai, h2.y, wi.y);
            ffma2(af, h2.x, wf.x); ffma2(af, h2.y, wf.y);
            ffma2(ag, h2.x, wg.x); ffma2(ag, h2.y, wg.y);
            ffma2(ao, h2.x, wo.x); ffma2(ao, h2.y, wo.y);
        }

        float gi = sigmoidf_(xi  + pairsum(ai));
        float gf = sigmoidf_(xf  + pairsum(af));
        float gg = tanhf    (xgg + pairsum(ag));
        float go = sigmoidf_(xo  + pairsum(ao));
        c = gf * c + gi * gg;
        float h = go * tanhf(c);
        __stcg(&g_h[(t + 1) & 1][b * HH + j], h);
        g_hs[((size_t)t * BB + b) * HH + j] = h;
        grid_barrier();    // release h-writes, protect hsm reuse
    }
}

// ---------------------------------------------------------------------------
// Phase 3: out[b][t][c] = hs[t][b][:] . W_fc[c][:] + b_fc[c]  (unchanged)
// ---------------------------------------------------------------------------
__global__ void __launch_bounds__(256) fc_gemm(
    const float* __restrict__ W_fc,
    const float* __restrict__ b_fc,
    float* __restrict__ out)
{
    __shared__ float As[8][128];
    __shared__ float Bs[8][128];

    const int m0 = blockIdx.x * 128;
    const int tid = threadIdx.x;
    const int tx = tid & 15;
    const int ty = tid >> 4;

    float acc[8][8];
#pragma unroll
    for (int i = 0; i < 8; i++)
#pragma unroll
        for (int j = 0; j < 8; j++) acc[i][j] = 0.0f;

    const int lr = tid >> 1;
    const int lk = (tid & 1) * 4;

    for (int k0 = 0; k0 < HH; k0 += 8) {
        {
            float4 v = *(const float4*)(g_hs + (size_t)(m0 + lr) * HH + k0 + lk);
            As[lk + 0][lr] = v.x; As[lk + 1][lr] = v.y;
            As[lk + 2][lr] = v.z; As[lk + 3][lr] = v.w;
        }
        {
            float4 v = *(const float4*)(W_fc + (size_t)lr * HH + k0 + lk);
            Bs[lk + 0][lr] = v.x; Bs[lk + 1][lr] = v.y;
            Bs[lk + 2][lr] = v.z; Bs[lk + 3][lr] = v.w;
        }
        __syncthreads();
#pragma unroll
        for (int k = 0; k < 8; k++) {
            float a[8], b[8];
            float4 a0 = *(const float4*)&As[k][ty * 4];
            float4 a1 = *(const float4*)&As[k][64 + ty * 4];
            float4 b0 = *(const float4*)&Bs[k][tx * 4];
            float4 b1 = *(const float4*)&Bs[k][64 + tx * 4];
            a[0]=a0.x; a[1]=a0.y; a[2]=a0.z; a[3]=a0.w;
            a[4]=a1.x; a[5]=a1.y; a[6]=a1.z; a[7]=a1.w;
            b[0]=b0.x; b[1]=b0.y; b[2]=b0.z; b[3]=b0.w;
            b[4]=b1.x; b[5]=b1.y; b[6]=b1.z; b[7]=b1.w;
#pragma unroll
            for (int i = 0; i < 8; i++)
#pragma unroll
                for (int j = 0; j < 8; j++)
                    acc[i][j] = fmaf(a[i], b[j], acc[i][j]);
        }
        __syncthreads();
    }

#pragma unroll
    for (int i = 0; i < 8; i++) {
        int m = m0 + (i >> 2) * 64 + ty * 4 + (i & 3);
        int bb = m & 63;
        int tt = m >> 6;
        size_t orow = ((size_t)bb * TT + tt) * CC;
#pragma unroll
        for (int j = 0; j < 8; j++) {
            int cc = (j >> 2) * 64 + tx * 4 + (j & 3);
            out[orow + cc] = acc[i][j] + b_fc[cc];
        }
    }
}

// ---------------------------------------------------------------------------
extern "C" void kernel_launch(void* const* d_in, const int* in_sizes, int n_in,
                              void* d_out, int out_size)
{
    const float* x    = (const float*)d_in[0];
    const float* W_ih = (const float*)d_in[1];
    const float* W_hh = (const float*)d_in[2];
    const float* b_ih = (const float*)d_in[3];
    const float* b_hh = (const float*)d_in[4];
    const float* W_fc = (const float*)d_in[5];
    const float* b_fc = (const float*)d_in[6];
    float* out = (float*)d_out;

    cudaFuncSetAttribute(lstm_recur,
                         cudaFuncAttributeMaxDynamicSharedMemorySize,
                         SMEM_RECUR);

    dim3 g1(4 * HH / 128, (BB * TT) / 128);   // (16, 256)
    gates_gemm<<<g1, 256>>>(x, W_ih, b_ih, b_hh);

    lstm_recur<<<128, 256, SMEM_RECUR>>>(W_hh);   // 128 CTAs, co-resident

    fc_gemm<<<(BB * TT) / 128, 256>>>(W_fc, b_fc, out);
}